// round 14
// baseline (speedup 1.0000x reference)
#include <cuda_runtime.h>
#include <cuda_fp16.h>
#include <cstdint>

#define BB     8192
#define DIN    64
#define DMID   1024
#define DOUT   64
#define KDOM   4
#define PADDED 9216
#define MT128  72
#define NKMID  16
#define TILE_E 8192
#define TILE_B 16384

// weight scratch elem offsets (fp16 elems, single plane)
#define OFF_W1  0L
#define OFF_W2  65536L
#define OFF_W3  1114112L
#define OFF_W4  2162688L
#define OFF_BW1 3211264L
#define OFF_BW2 7405568L
#define OFF_BW3 11599872L
#define OFF_BW4 15794176L
#define WTOT    16056320L

__device__ int g_perm[PADDED];
__device__ int g_seg[KDOM + 1];
__device__ int g_cnt[KDOM];

__device__ float4 g_w4[WTOT / 8];                 // weights fp16
__device__ float4 g_x4[73728];                    // X fp16
__device__ float4 g_a4[1179648], g_b4[1179648];   // activations ping/pong

__device__ __forceinline__ uint32_t smem_u32(const void* p) {
    uint32_t a;
    asm("{ .reg .u64 t; cvta.to.shared.u64 t, %1; cvt.u32.u64 %0, t; }" : "=r"(a) : "l"(p));
    return a;
}
#define SW128(b) ((b) ^ (((b) >> 3) & 0x70))
#define CP16(s, g)  asm volatile("cp.async.cg.shared.global [%0], [%1], 16;" :: "r"(s), "l"(g))
#define CPCOMMIT()  asm volatile("cp.async.commit_group;" ::: "memory")
#define CPWAIT(n)   asm volatile("cp.async.wait_group %0;" :: "n"(n) : "memory")

#define LDSM4(r0,r1,r2,r3,a) \
    asm volatile("ldmatrix.sync.aligned.m8n8.x4.shared.b16 {%0,%1,%2,%3}, [%4];" \
        : "=r"(r0),"=r"(r1),"=r"(r2),"=r"(r3) : "r"(a))
#define MMA(d,a,b) \
    asm volatile("mma.sync.aligned.m16n8k16.row.col.f32.f16.f16.f32 " \
        "{%0,%1,%2,%3}, {%4,%5,%6,%7}, {%8,%9}, {%0,%1,%2,%3};" \
        : "+f"((d)[0]),"+f"((d)[1]),"+f"((d)[2]),"+f"((d)[3]) \
        : "r"((a)[0]),"r"((a)[1]),"r"((a)[2]),"r"((a)[3]),"r"((b)[0]),"r"((b)[1]))

// ---------------------------------------------------------------- setup (R12 clean version)
__global__ void setup_kernel(const int* __restrict__ domains) {
    __shared__ int cnt[KDOM];
    int t = threadIdx.x;
    if (t < KDOM) cnt[t] = 0;
    __syncthreads();
    for (int i = t; i < BB; i += blockDim.x)
        atomicAdd(&cnt[domains[i] & (KDOM - 1)], 1);
    for (int i = t; i < PADDED; i += blockDim.x) g_perm[i] = -1;
    __syncthreads();
    if (t == 0) {
        int off = 0;
        for (int d = 0; d < KDOM; d++) {
            g_seg[d] = off; g_cnt[d] = 0;
            off += (cnt[d] + 255) / 256 * 256;
        }
        g_seg[KDOM] = off;
    }
}
__global__ void build_perm_kernel(const int* __restrict__ domains) {
    int i = blockIdx.x * blockDim.x + threadIdx.x;
    if (i < BB) {
        int d = domains[i] & (KDOM - 1);
        int pos = g_seg[d] + atomicAdd(&g_cnt[d], 1);
        if (pos >= 0 && pos < PADDED) g_perm[pos] = i;
    }
}

// ------------------------------------------------ X prep: gather+round+swizzle (vectorized)
__global__ void prep_x(const float* __restrict__ X) {
    __shared__ __align__(16) char sm[16384];
    int mt = blockIdx.x;
    for (int e4 = threadIdx.x; e4 < 2048; e4 += 256) {
        int r = e4 >> 4, c4 = e4 & 15;
        int s = g_perm[mt * 128 + r];
        float4 v = (s >= 0) ? *(const float4*)(X + (long)s * DIN + c4 * 4)
                            : make_float4(0.f, 0.f, 0.f, 0.f);
        int c = c4 * 4;
        uint32_t b0 = (uint32_t)(r * 128);
        *(uint16_t*)(sm + SW128(b0 + (c + 0) * 2)) = __half_as_ushort(__float2half_rn(v.x));
        *(uint16_t*)(sm + SW128(b0 + (c + 1) * 2)) = __half_as_ushort(__float2half_rn(v.y));
        *(uint16_t*)(sm + SW128(b0 + (c + 2) * 2)) = __half_as_ushort(__float2half_rn(v.z));
        *(uint16_t*)(sm + SW128(b0 + (c + 3) * 2)) = __half_as_ushort(__float2half_rn(v.w));
    }
    __syncthreads();
    const float4* s4 = (const float4*)sm;
    for (int i = threadIdx.x; i < 1024; i += 256)
        g_x4[mt * 1024 + i] = s4[i];
}

// ------------------------------------------------ weight prep (fp16 round, vectorized)
struct WMeta { const float* src; long dst; int kch, N, TNt, shift; };
struct WArgs { WMeta m[20]; };
__global__ void prep_w(WArgs a) {
    WMeta w = a.m[blockIdx.y];
    int ntiles = w.N / w.TNt;
    int tile = blockIdx.x;
    if (tile >= w.kch * ntiles) return;
    int nt = tile / w.kch, kc = tile - nt * w.kch;
    __shared__ __align__(16) char sm[16384];
    int elems = w.TNt * 64;
    int n4cnt = w.TNt / 4;
    int tot4  = elems / 4;
    for (int e4 = threadIdx.x; e4 < tot4; e4 += 256) {
        int n4 = e4 % n4cnt, k = e4 / n4cnt;
        int n = n4 * 4;
        float4 v = *(const float4*)(w.src + (long)(kc * 64 + k) * w.N + nt * w.TNt + n);
        uint32_t k2 = (uint32_t)(k * 2);
        *(uint16_t*)(sm + SW128((uint32_t)((n + 0) * 128) + k2)) = __half_as_ushort(__float2half_rn(v.x));
        *(uint16_t*)(sm + SW128((uint32_t)((n + 1) * 128) + k2)) = __half_as_ushort(__float2half_rn(v.y));
        *(uint16_t*)(sm + SW128((uint32_t)((n + 2) * 128) + k2)) = __half_as_ushort(__float2half_rn(v.z));
        *(uint16_t*)(sm + SW128((uint32_t)((n + 3) * 128) + k2)) = __half_as_ushort(__float2half_rn(v.w));
    }
    __syncthreads();
    long delem = w.dst + (long)tile * elems;
    const float4* s4 = (const float4*)sm;
    float4* dh = (float4*)((__half*)g_w4 + delem);
    int n4 = elems / 8;
    for (int i = threadIdx.x; i < n4; i += 256) dh[i] = s4[i];
}

// ------------------------------------------------ mma.sync GEMM (R12 + padding-tile early exit)
template<int NK, int NTC, bool LAST>
__global__ void __launch_bounds__(256, 2)
gemm_tc(int a_sel, long woff, long wstride, const float* __restrict__ bias,
        int bstride, int c_sel, float* __restrict__ out)
{
    constexpr int TN   = 4 * NTC;
    constexpr int TNB  = TN * 128;
    constexpr int STGB = 16384 + TNB;
    constexpr int NTT  = NTC / 8;
    constexpr int NLD  = NTC / 16;
    extern __shared__ char smem[];
    const uint32_t sb = smem_u32(smem);

    const int tid = threadIdx.x;
    const int lane = tid & 31, wid = tid >> 5;
    const int wm = wid & 1, wn = wid >> 1;
    const int ntile = LAST ? 0 : blockIdx.x;
    const int mtile = LAST ? blockIdx.x : blockIdx.y;
    const int m0 = mtile * 128, n0 = ntile * TN;

    // padding-tile skip: rows >= g_seg[KDOM] are never read by real outputs
    if (m0 >= g_seg[KDOM]) return;

    int dom = 0;
#pragma unroll
    for (int d = 1; d < KDOM; d++) if (m0 >= g_seg[d]) dom = d;
    const __half* wp = (const __half*)g_w4 + woff + dom * wstride;
    const float* bptr = bias + (long)dom * bstride;

    const float4* Ap = (a_sel == 0) ? g_x4 : (a_sel == 1) ? g_a4 : g_b4;
    char* Cp = (char*)((c_sel == 1) ? g_a4 : g_b4);

    const int lane16 = lane & 15;
    const uint32_t axk = ((lane >> 4) & 1) << 4;
    uint32_t aoff[4], arx[4];
#pragma unroll
    for (int mt = 0; mt < 4; mt++) {
        int r = wm * 64 + mt * 16 + lane16;
        aoff[mt] = r * 128; arx[mt] = (r & 7) << 4;
    }
    uint32_t boff[NLD], brx[NLD];
#pragma unroll
    for (int p = 0; p < NLD; p++) {
        int nl = wn * NTC + p * 16 + lane16;
        boff[p] = nl * 128; brx[p] = (nl & 7) << 4;
    }

    float acc[4][NTT][4];
#pragma unroll
    for (int mt = 0; mt < 4; mt++)
#pragma unroll
        for (int nt = 0; nt < NTT; nt++)
#pragma unroll
            for (int q = 0; q < 4; q++) acc[mt][nt][q] = 0.f;

    auto load_stage = [&](int st, int kc) {
        uint32_t s0 = sb + st * STGB;
        const float4* ta = Ap + ((long)mtile * NK + kc) * 1024;
#pragma unroll
        for (int i = 0; i < 4; i++) {
            int t = tid + i * 256;
            CP16(s0 + t * 16, ta + t);
        }
        const float4* bh = (const float4*)(wp + ((long)ntile * NK + kc) * (long)(TN * 64));
#pragma unroll
        for (int i = 0; i < TN / 32; i++) {
            int t = tid + i * 256;
            CP16(s0 + 16384 + t * 16, bh + t);
        }
    };

    load_stage(0, 0); CPCOMMIT();
    if (NK > 1) { load_stage(1, 1); CPCOMMIT(); }

    for (int kc = 0; kc < NK; kc++) {
        if (kc + 1 < NK) { CPWAIT(1); } else { CPWAIT(0); }
        __syncthreads();
        const uint32_t sA = sb + (kc & 1) * STGB;
        const uint32_t sB = sA + 16384;
#pragma unroll
        for (int ks = 0; ks < 4; ks++) {
            const uint32_t cb = ks << 5;
            uint32_t bf[NTT][2];
#pragma unroll
            for (int p = 0; p < NLD; p++) {
                uint32_t r0, r1, r2, r3;
                LDSM4(r0, r1, r2, r3, sB + boff[p] + ((cb | axk) ^ brx[p]));
                bf[2*p  ][0] = r0; bf[2*p  ][1] = r2;
                bf[2*p+1][0] = r1; bf[2*p+1][1] = r3;
            }
#pragma unroll
            for (int mt = 0; mt < 4; mt++) {
                uint32_t ah[4];
                LDSM4(ah[0], ah[1], ah[2], ah[3],
                      sA + aoff[mt] + ((cb | axk) ^ arx[mt]));
#pragma unroll
                for (int nt = 0; nt < NTT; nt++)
                    MMA(acc[mt][nt], ah, bf[nt]);
            }
        }
        if (kc + 2 < NK) {
            __syncthreads();
            load_stage(kc & 1, kc + 2); CPCOMMIT();
        }
    }

    const int rq = lane >> 2, cq = (lane & 3) * 2;
    if (!LAST) {
#pragma unroll
        for (int mt = 0; mt < 4; mt++) {
            int rA = wm * 64 + mt * 16 + rq;
#pragma unroll
            for (int nt = 0; nt < NTT; nt++) {
                int c = wn * NTC + (nt >> 1) * 16 + (nt & 1) * 8 + cq;
                int gc = n0 + c;
                float b0 = __ldg(bptr + gc), b1 = __ldg(bptr + gc + 1);
#pragma unroll
                for (int h = 0; h < 2; h++) {
                    int r = rA + h * 8;
                    float v0 = fmaxf(acc[mt][nt][h * 2 + 0] + b0, 0.f);
                    float v1 = fmaxf(acc[mt][nt][h * 2 + 1] + b1, 0.f);
                    uint16_t h0 = __half_as_ushort(__float2half_rn(v0));
                    uint16_t h1 = __half_as_ushort(__float2half_rn(v1));
                    long tb = ((long)mtile * NKMID + (gc >> 6)) * TILE_B;
                    uint32_t phys = (uint32_t)(r * 128) +
                                    (((uint32_t)((gc & 63) * 2)) ^ ((r & 7) << 4));
                    *(uint32_t*)(Cp + tb + phys) = (uint32_t)h0 | ((uint32_t)h1 << 16);
                }
            }
        }
    } else {
#pragma unroll
        for (int mt = 0; mt < 4; mt++) {
            int rA = wm * 64 + mt * 16 + rq;
#pragma unroll
            for (int h = 0; h < 2; h++) {
                int r = rA + h * 8;
                int src = g_perm[m0 + r];
                if (src >= 0) {
#pragma unroll
                    for (int nt = 0; nt < NTT; nt++) {
                        int c = wn * NTC + (nt >> 1) * 16 + (nt & 1) * 8 + cq;
                        float2 v;
                        v.x = acc[mt][nt][h * 2 + 0] + __ldg(bptr + c);
                        v.y = acc[mt][nt][h * 2 + 1] + __ldg(bptr + c + 1);
                        *(float2*)(out + (long)src * DOUT + c) = v;
                    }
                }
            }
        }
    }
}

// ----------------------------------------------------------------
extern "C" void kernel_launch(void* const* d_in, const int* in_sizes, int n_in,
                              void* d_out, int out_size)
{
    const float* X   = (const float*)d_in[0];
    const int*   dom = (const int*)d_in[1];
    const float *W1 = (const float*)d_in[2],  *b1  = (const float*)d_in[3];
    const float *W2 = (const float*)d_in[4],  *b2  = (const float*)d_in[5];
    const float *W3 = (const float*)d_in[6],  *b3  = (const float*)d_in[7];
    const float *W4 = (const float*)d_in[8],  *b4  = (const float*)d_in[9];
    const float *BW1 = (const float*)d_in[10], *Bb1 = (const float*)d_in[11];
    const float *BW2 = (const float*)d_in[12], *Bb2 = (const float*)d_in[13];
    const float *BW3 = (const float*)d_in[14], *Bb3 = (const float*)d_in[15];
    const float *BW4 = (const float*)d_in[16], *Bb4 = (const float*)d_in[17];
    float* out = (float*)d_out;

    const int SM_MID = 2 * (16384 + 16384);   // 65536 per CTA
    const int SM_LST = 2 * (16384 + 8192);    // 49152 per CTA
    cudaFuncSetAttribute(gemm_tc<1, 32, false>,  cudaFuncAttributeMaxDynamicSharedMemorySize, SM_MID);
    cudaFuncSetAttribute(gemm_tc<16, 32, false>, cudaFuncAttributeMaxDynamicSharedMemorySize, SM_MID);
    cudaFuncSetAttribute(gemm_tc<16, 16, true>,  cudaFuncAttributeMaxDynamicSharedMemorySize, SM_LST);

    setup_kernel<<<1, 1024>>>(dom);
    build_perm_kernel<<<(BB + 255) / 256, 256>>>(dom);
    prep_x<<<MT128, 256>>>(X);

    WArgs wa;
    int idx = 0;
    wa.m[idx++] = {W1, OFF_W1, 1, DMID, 128, 7};
    wa.m[idx++] = {W2, OFF_W2, 16, DMID, 128, 7};
    wa.m[idx++] = {W3, OFF_W3, 16, DMID, 128, 7};
    wa.m[idx++] = {W4, OFF_W4, 16, DMID, 128, 7};
    for (int d = 0; d < 4; d++) wa.m[idx++] = {BW1 + (long)d*1048576, OFF_BW1 + (long)d*1048576, 16, DMID, 128, 7};
    for (int d = 0; d < 4; d++) wa.m[idx++] = {BW2 + (long)d*1048576, OFF_BW2 + (long)d*1048576, 16, DMID, 128, 7};
    for (int d = 0; d < 4; d++) wa.m[idx++] = {BW3 + (long)d*1048576, OFF_BW3 + (long)d*1048576, 16, DMID, 128, 7};
    for (int d = 0; d < 4; d++) wa.m[idx++] = {BW4 + (long)d*65536,   OFF_BW4 + (long)d*65536,   16, DOUT, 64, 6};
    prep_w<<<dim3(128, 20), 256>>>(wa);

    dim3 g(8, MT128);
    gemm_tc<1, 32, false> <<<g, 256, SM_MID>>>(0, OFF_W1, 0, b1, 0, 1, nullptr);
    gemm_tc<16, 32, false><<<g, 256, SM_MID>>>(1, OFF_W2, 0, b2, 0, 2, nullptr);
    gemm_tc<16, 32, false><<<g, 256, SM_MID>>>(2, OFF_W3, 0, b3, 0, 1, nullptr);
    gemm_tc<16, 32, false><<<g, 256, SM_MID>>>(1, OFF_W4, 0, b4, 0, 2, nullptr);
    gemm_tc<16, 32, false><<<g, 256, SM_MID>>>(2, OFF_BW1, 1048576L, Bb1, DMID, 1, nullptr);
    gemm_tc<16, 32, false><<<g, 256, SM_MID>>>(1, OFF_BW2, 1048576L, Bb2, DMID, 2, nullptr);
    gemm_tc<16, 32, false><<<g, 256, SM_MID>>>(2, OFF_BW3, 1048576L, Bb3, DMID, 1, nullptr);
    gemm_tc<16, 16, true> <<<MT128, 256, SM_LST>>>(1, OFF_BW4, 65536L, Bb4, 64, 0, out);
}

// round 15
// speedup vs baseline: 1.0477x; 1.0477x over previous
#include <cuda_runtime.h>
#include <cuda_fp16.h>
#include <cstdint>

#define BB     8192
#define DIN    64
#define DMID   1024
#define DOUT   64
#define KDOM   4
#define PADDED 9216
#define MT128  72
#define NKMID  16
#define TILE_E 8192
#define TILE_B 16384

// weight scratch elem offsets (fp16 elems, single plane)
#define OFF_W1  0L
#define OFF_W2  65536L
#define OFF_W3  1114112L
#define OFF_W4  2162688L
#define OFF_BW1 3211264L
#define OFF_BW2 7405568L
#define OFF_BW3 11599872L
#define OFF_BW4 15794176L
#define WTOT    16056320L

__device__ int g_perm[PADDED];
__device__ int g_seg[KDOM + 1];
__device__ int g_cnt[KDOM];

__device__ float4 g_w4[WTOT / 8];                 // weights fp16
__device__ float4 g_x4[73728];                    // X fp16
__device__ float4 g_a4[1179648], g_b4[1179648];   // activations ping/pong

__device__ __forceinline__ uint32_t smem_u32(const void* p) {
    uint32_t a;
    asm("{ .reg .u64 t; cvta.to.shared.u64 t, %1; cvt.u32.u64 %0, t; }" : "=r"(a) : "l"(p));
    return a;
}
#define SW128(b) ((b) ^ (((b) >> 3) & 0x70))
#define CP16(s, g)  asm volatile("cp.async.cg.shared.global [%0], [%1], 16;" :: "r"(s), "l"(g))
#define CPCOMMIT()  asm volatile("cp.async.commit_group;" ::: "memory")
#define CPWAIT(n)   asm volatile("cp.async.wait_group %0;" :: "n"(n) : "memory")

#define LDSM4(r0,r1,r2,r3,a) \
    asm volatile("ldmatrix.sync.aligned.m8n8.x4.shared.b16 {%0,%1,%2,%3}, [%4];" \
        : "=r"(r0),"=r"(r1),"=r"(r2),"=r"(r3) : "r"(a))
#define MMA(d,a,b) \
    asm volatile("mma.sync.aligned.m16n8k16.row.col.f32.f16.f16.f32 " \
        "{%0,%1,%2,%3}, {%4,%5,%6,%7}, {%8,%9}, {%0,%1,%2,%3};" \
        : "+f"((d)[0]),"+f"((d)[1]),"+f"((d)[2]),"+f"((d)[3]) \
        : "r"((a)[0]),"r"((a)[1]),"r"((a)[2]),"r"((a)[3]),"r"((b)[0]),"r"((b)[1]))

__device__ __forceinline__ uint32_t pack2h(float a, float b) {
    return (uint32_t)__half_as_ushort(__float2half_rn(a)) |
           ((uint32_t)__half_as_ushort(__float2half_rn(b)) << 16);
}

// ---------------------------------------------------------------- setup
__global__ void setup_kernel(const int* __restrict__ domains) {
    __shared__ int cnt[KDOM];
    int t = threadIdx.x;
    if (t < KDOM) cnt[t] = 0;
    __syncthreads();
    for (int i = t; i < BB; i += blockDim.x)
        atomicAdd(&cnt[domains[i] & (KDOM - 1)], 1);
    for (int i = t; i < PADDED; i += blockDim.x) g_perm[i] = -1;
    __syncthreads();
    if (t == 0) {
        int off = 0;
        for (int d = 0; d < KDOM; d++) {
            g_seg[d] = off; g_cnt[d] = 0;
            off += (cnt[d] + 255) / 256 * 256;
        }
        g_seg[KDOM] = off;
    }
}
__global__ void build_perm_kernel(const int* __restrict__ domains) {
    int i = blockIdx.x * blockDim.x + threadIdx.x;
    if (i < BB) {
        int d = domains[i] & (KDOM - 1);
        int pos = g_seg[d] + atomicAdd(&g_cnt[d], 1);
        if (pos >= 0 && pos < PADDED) g_perm[pos] = i;
    }
}

// ------------------------------------------------ X prep: one (row, k8) per thread
__global__ void prep_x(const float* __restrict__ X) {
    __shared__ __align__(16) char sm[16384];
    int mt = blockIdx.x;
    // 128 rows x 8 k8-groups = 1024 items
    for (int e = threadIdx.x; e < 1024; e += 256) {
        int r = e >> 3, k8 = e & 7;
        int s = g_perm[mt * 128 + r];
        uint4 v = make_uint4(0, 0, 0, 0);
        if (s >= 0) {
            const float* row = X + (long)s * DIN + k8 * 8;
            float4 f0 = *(const float4*)(row);
            float4 f1 = *(const float4*)(row + 4);
            v.x = pack2h(f0.x, f0.y); v.y = pack2h(f0.z, f0.w);
            v.z = pack2h(f1.x, f1.y); v.w = pack2h(f1.z, f1.w);
        }
        *(uint4*)(sm + SW128((uint32_t)(r * 128 + k8 * 16))) = v;
    }
    __syncthreads();
    const float4* s4 = (const float4*)sm;
    for (int i = threadIdx.x; i < 1024; i += 256)
        g_x4[mt * 1024 + i] = s4[i];
}

// ------------------------------------------------ weight prep: one (n, k8) per thread
struct WMeta { const float* src; long dst; int kch, N, TNt, shift; };
struct WArgs { WMeta m[20]; };
__global__ void prep_w(WArgs a) {
    WMeta w = a.m[blockIdx.y];
    int ntiles = w.N / w.TNt;
    int tile = blockIdx.x;
    if (tile >= w.kch * ntiles) return;
    int nt = tile / w.kch, kc = tile - nt * w.kch;
    __shared__ __align__(16) char sm[16384];
    int items = w.TNt * 8;             // (n, k8) pairs
    for (int e = threadIdx.x; e < items; e += 256) {
        int n = e % w.TNt, k8 = e / w.TNt;
        const float* src = w.src + (long)(kc * 64 + k8 * 8) * w.N + nt * w.TNt + n;
        float f[8];
#pragma unroll
        for (int j = 0; j < 8; j++) f[j] = src[(long)j * w.N];
        uint4 v;
        v.x = pack2h(f[0], f[1]); v.y = pack2h(f[2], f[3]);
        v.z = pack2h(f[4], f[5]); v.w = pack2h(f[6], f[7]);
        *(uint4*)(sm + SW128((uint32_t)(n * 128 + k8 * 16))) = v;
    }
    __syncthreads();
    int elems = w.TNt * 64;
    long delem = w.dst + (long)tile * elems;
    const float4* s4 = (const float4*)sm;
    float4* dh = (float4*)((__half*)g_w4 + delem);
    int n4 = elems / 8;
    for (int i = threadIdx.x; i < n4; i += 256) dh[i] = s4[i];
}

// ------------------------------------------------ mma.sync GEMM (R12 + early exit)
template<int NK, int NTC, bool LAST>
__global__ void __launch_bounds__(256, 2)
gemm_tc(int a_sel, long woff, long wstride, const float* __restrict__ bias,
        int bstride, int c_sel, float* __restrict__ out)
{
    constexpr int TN   = 4 * NTC;
    constexpr int TNB  = TN * 128;
    constexpr int STGB = 16384 + TNB;
    constexpr int NTT  = NTC / 8;
    constexpr int NLD  = NTC / 16;
    extern __shared__ char smem[];
    const uint32_t sb = smem_u32(smem);

    const int tid = threadIdx.x;
    const int lane = tid & 31, wid = tid >> 5;
    const int wm = wid & 1, wn = wid >> 1;
    const int ntile = LAST ? 0 : blockIdx.x;
    const int mtile = LAST ? blockIdx.x : blockIdx.y;
    const int m0 = mtile * 128, n0 = ntile * TN;

    if (m0 >= g_seg[KDOM]) return;   // padding tiles: rows never read

    int dom = 0;
#pragma unroll
    for (int d = 1; d < KDOM; d++) if (m0 >= g_seg[d]) dom = d;
    const __half* wp = (const __half*)g_w4 + woff + dom * wstride;
    const float* bptr = bias + (long)dom * bstride;

    const float4* Ap = (a_sel == 0) ? g_x4 : (a_sel == 1) ? g_a4 : g_b4;
    char* Cp = (char*)((c_sel == 1) ? g_a4 : g_b4);

    const int lane16 = lane & 15;
    const uint32_t axk = ((lane >> 4) & 1) << 4;
    uint32_t aoff[4], arx[4];
#pragma unroll
    for (int mt = 0; mt < 4; mt++) {
        int r = wm * 64 + mt * 16 + lane16;
        aoff[mt] = r * 128; arx[mt] = (r & 7) << 4;
    }
    uint32_t boff[NLD], brx[NLD];
#pragma unroll
    for (int p = 0; p < NLD; p++) {
        int nl = wn * NTC + p * 16 + lane16;
        boff[p] = nl * 128; brx[p] = (nl & 7) << 4;
    }

    float acc[4][NTT][4];
#pragma unroll
    for (int mt = 0; mt < 4; mt++)
#pragma unroll
        for (int nt = 0; nt < NTT; nt++)
#pragma unroll
            for (int q = 0; q < 4; q++) acc[mt][nt][q] = 0.f;

    auto load_stage = [&](int st, int kc) {
        uint32_t s0 = sb + st * STGB;
        const float4* ta = Ap + ((long)mtile * NK + kc) * 1024;
#pragma unroll
        for (int i = 0; i < 4; i++) {
            int t = tid + i * 256;
            CP16(s0 + t * 16, ta + t);
        }
        const float4* bh = (const float4*)(wp + ((long)ntile * NK + kc) * (long)(TN * 64));
#pragma unroll
        for (int i = 0; i < TN / 32; i++) {
            int t = tid + i * 256;
            CP16(s0 + 16384 + t * 16, bh + t);
        }
    };

    load_stage(0, 0); CPCOMMIT();
    if (NK > 1) { load_stage(1, 1); CPCOMMIT(); }

    for (int kc = 0; kc < NK; kc++) {
        if (kc + 1 < NK) { CPWAIT(1); } else { CPWAIT(0); }
        __syncthreads();
        const uint32_t sA = sb + (kc & 1) * STGB;
        const uint32_t sB = sA + 16384;
#pragma unroll
        for (int ks = 0; ks < 4; ks++) {
            const uint32_t cb = ks << 5;
            uint32_t bf[NTT][2];
#pragma unroll
            for (int p = 0; p < NLD; p++) {
                uint32_t r0, r1, r2, r3;
                LDSM4(r0, r1, r2, r3, sB + boff[p] + ((cb | axk) ^ brx[p]));
                bf[2*p  ][0] = r0; bf[2*p  ][1] = r2;
                bf[2*p+1][0] = r1; bf[2*p+1][1] = r3;
            }
#pragma unroll
            for (int mt = 0; mt < 4; mt++) {
                uint32_t ah[4];
                LDSM4(ah[0], ah[1], ah[2], ah[3],
                      sA + aoff[mt] + ((cb | axk) ^ arx[mt]));
#pragma unroll
                for (int nt = 0; nt < NTT; nt++)
                    MMA(acc[mt][nt], ah, bf[nt]);
            }
        }
        if (kc + 2 < NK) {
            __syncthreads();
            load_stage(kc & 1, kc + 2); CPCOMMIT();
        }
    }

    const int rq = lane >> 2, cq = (lane & 3) * 2;
    if (!LAST) {
#pragma unroll
        for (int mt = 0; mt < 4; mt++) {
            int rA = wm * 64 + mt * 16 + rq;
#pragma unroll
            for (int nt = 0; nt < NTT; nt++) {
                int c = wn * NTC + (nt >> 1) * 16 + (nt & 1) * 8 + cq;
                int gc = n0 + c;
                float b0 = __ldg(bptr + gc), b1 = __ldg(bptr + gc + 1);
#pragma unroll
                for (int h = 0; h < 2; h++) {
                    int r = rA + h * 8;
                    float v0 = fmaxf(acc[mt][nt][h * 2 + 0] + b0, 0.f);
                    float v1 = fmaxf(acc[mt][nt][h * 2 + 1] + b1, 0.f);
                    long tb = ((long)mtile * NKMID + (gc >> 6)) * TILE_B;
                    uint32_t phys = (uint32_t)(r * 128) +
                                    (((uint32_t)((gc & 63) * 2)) ^ ((r & 7) << 4));
                    *(uint32_t*)(Cp + tb + phys) = pack2h(v0, v1);
                }
            }
        }
    } else {
#pragma unroll
        for (int mt = 0; mt < 4; mt++) {
            int rA = wm * 64 + mt * 16 + rq;
#pragma unroll
            for (int h = 0; h < 2; h++) {
                int r = rA + h * 8;
                int src = g_perm[m0 + r];
                if (src >= 0) {
#pragma unroll
                    for (int nt = 0; nt < NTT; nt++) {
                        int c = wn * NTC + (nt >> 1) * 16 + (nt & 1) * 8 + cq;
                        float2 v;
                        v.x = acc[mt][nt][h * 2 + 0] + __ldg(bptr + c);
                        v.y = acc[mt][nt][h * 2 + 1] + __ldg(bptr + c + 1);
                        *(float2*)(out + (long)src * DOUT + c) = v;
                    }
                }
            }
        }
    }
}

// ----------------------------------------------------------------
extern "C" void kernel_launch(void* const* d_in, const int* in_sizes, int n_in,
                              void* d_out, int out_size)
{
    const float* X   = (const float*)d_in[0];
    const int*   dom = (const int*)d_in[1];
    const float *W1 = (const float*)d_in[2],  *b1  = (const float*)d_in[3];
    const float *W2 = (const float*)d_in[4],  *b2  = (const float*)d_in[5];
    const float *W3 = (const float*)d_in[6],  *b3  = (const float*)d_in[7];
    const float *W4 = (const float*)d_in[8],  *b4  = (const float*)d_in[9];
    const float *BW1 = (const float*)d_in[10], *Bb1 = (const float*)d_in[11];
    const float *BW2 = (const float*)d_in[12], *Bb2 = (const float*)d_in[13];
    const float *BW3 = (const float*)d_in[14], *Bb3 = (const float*)d_in[15];
    const float *BW4 = (const float*)d_in[16], *Bb4 = (const float*)d_in[17];
    float* out = (float*)d_out;

    const int SM_MID = 2 * (16384 + 16384);   // 65536 per CTA
    const int SM_LST = 2 * (16384 + 8192);    // 49152 per CTA
    cudaFuncSetAttribute(gemm_tc<1, 32, false>,  cudaFuncAttributeMaxDynamicSharedMemorySize, SM_MID);
    cudaFuncSetAttribute(gemm_tc<16, 32, false>, cudaFuncAttributeMaxDynamicSharedMemorySize, SM_MID);
    cudaFuncSetAttribute(gemm_tc<16, 16, true>,  cudaFuncAttributeMaxDynamicSharedMemorySize, SM_LST);

    setup_kernel<<<1, 1024>>>(dom);
    build_perm_kernel<<<(BB + 255) / 256, 256>>>(dom);
    prep_x<<<MT128, 256>>>(X);

    WArgs wa;
    int idx = 0;
    wa.m[idx++] = {W1, OFF_W1, 1, DMID, 128, 7};
    wa.m[idx++] = {W2, OFF_W2, 16, DMID, 128, 7};
    wa.m[idx++] = {W3, OFF_W3, 16, DMID, 128, 7};
    wa.m[idx++] = {W4, OFF_W4, 16, DMID, 128, 7};
    for (int d = 0; d < 4; d++) wa.m[idx++] = {BW1 + (long)d*1048576, OFF_BW1 + (long)d*1048576, 16, DMID, 128, 7};
    for (int d = 0; d < 4; d++) wa.m[idx++] = {BW2 + (long)d*1048576, OFF_BW2 + (long)d*1048576, 16, DMID, 128, 7};
    for (int d = 0; d < 4; d++) wa.m[idx++] = {BW3 + (long)d*1048576, OFF_BW3 + (long)d*1048576, 16, DMID, 128, 7};
    for (int d = 0; d < 4; d++) wa.m[idx++] = {BW4 + (long)d*65536,   OFF_BW4 + (long)d*65536,   16, DOUT, 64, 6};
    prep_w<<<dim3(128, 20), 256>>>(wa);

    dim3 g(8, MT128);
    gemm_tc<1, 32, false> <<<g, 256, SM_MID>>>(0, OFF_W1, 0, b1, 0, 1, nullptr);
    gemm_tc<16, 32, false><<<g, 256, SM_MID>>>(1, OFF_W2, 0, b2, 0, 2, nullptr);
    gemm_tc<16, 32, false><<<g, 256, SM_MID>>>(2, OFF_W3, 0, b3, 0, 1, nullptr);
    gemm_tc<16, 32, false><<<g, 256, SM_MID>>>(1, OFF_W4, 0, b4, 0, 2, nullptr);
    gemm_tc<16, 32, false><<<g, 256, SM_MID>>>(2, OFF_BW1, 1048576L, Bb1, DMID, 1, nullptr);
    gemm_tc<16, 32, false><<<g, 256, SM_MID>>>(1, OFF_BW2, 1048576L, Bb2, DMID, 2, nullptr);
    gemm_tc<16, 32, false><<<g, 256, SM_MID>>>(2, OFF_BW3, 1048576L, Bb3, DMID, 1, nullptr);
    gemm_tc<16, 16, true> <<<MT128, 256, SM_LST>>>(1, OFF_BW4, 65536L, Bb4, 64, 0, out);
}